// round 1
// baseline (speedup 1.0000x reference)
#include <cuda_runtime.h>
#include <cuda_bf16.h>

// FieldAwareFM: out[b] = sum over 780 field pairs (a<b) of
//   dot(x[b, a, b-1, :], x[b, b, a, :])  with x = input reshaped (bs, 40, 39, 16).
// Every (field, col) slot participates in exactly one pair, so we sum
// x[e] * x[partner(e)] over ALL elements and scale by 0.5.
//
// partner(f = i*39 + j) = (j+1)*39 + i   if j >= i   (upper; pair (i, j+1))
//                       = j*39 + (i-1)   if j <  i   (lower; pair (j, i))

#define NUM_FIELDS 40
#define COLS 39              // NUM_FIELDS - 1
#define EMB 16
#define ROW_FLOATS (NUM_FIELDS * COLS * EMB)   // 24960
#define ROW_F4 (ROW_FLOATS / 4)                // 6240
#define THREADS 256

__global__ __launch_bounds__(THREADS, 8)
void ffm_pair_dot_kernel(const float* __restrict__ in, float* __restrict__ out)
{
    const int b = blockIdx.x;
    const float4* __restrict__ row = reinterpret_cast<const float4*>(in) + (size_t)b * ROW_F4;

    float acc = 0.0f;

    // Each float4 index e4 = f*4 + d4, where f is the flat (field, col) slot
    // and d4 selects 4 of the 16 embedding floats. The partner float4 shares d4.
    #pragma unroll 4
    for (int e4 = threadIdx.x; e4 < ROW_F4; e4 += THREADS) {
        const int f  = e4 >> 2;
        const int d4 = e4 & 3;
        const int i  = f / COLS;          // ptxas emits magic-number IMAD
        const int j  = f - i * COLS;
        const int pf = (j >= i) ? ((j + 1) * COLS + i)
                                : (j * COLS + (i - 1));

        const float4 a = row[e4];
        const float4 p = __ldg(&row[pf * 4 + d4]);
        acc = fmaf(a.x, p.x, acc);
        acc = fmaf(a.y, p.y, acc);
        acc = fmaf(a.z, p.z, acc);
        acc = fmaf(a.w, p.w, acc);
    }

    // ---- block reduction: warp shuffle, then cross-warp via smem ----
    #pragma unroll
    for (int o = 16; o > 0; o >>= 1)
        acc += __shfl_down_sync(0xffffffffu, acc, o);

    __shared__ float warp_sums[THREADS / 32];
    if ((threadIdx.x & 31) == 0)
        warp_sums[threadIdx.x >> 5] = acc;
    __syncthreads();

    if (threadIdx.x < (THREADS / 32)) {
        acc = warp_sums[threadIdx.x];
        #pragma unroll
        for (int o = (THREADS / 64); o > 0; o >>= 1)
            acc += __shfl_down_sync(0x000000ffu, acc, o);
        if (threadIdx.x == 0)
            out[b] = 0.5f * acc;
    }
}

extern "C" void kernel_launch(void* const* d_in, const int* in_sizes, int n_in,
                              void* d_out, int out_size)
{
    const float* in = (const float*)d_in[0];
    float* out = (float*)d_out;
    const int bs = in_sizes[0] / ROW_FLOATS;   // 2048
    ffm_pair_dot_kernel<<<bs, THREADS>>>(in, out);
}